// round 2
// baseline (speedup 1.0000x reference)
#include <cuda_runtime.h>
#include <cstdint>

// Problem constants (from reference): N=100000, DIM=64, A=100, EPS=0.1, NUM_NEG=10
#define DIM        64
#define MAX_XELEMS (100000 * 64)

// 16B-aligned scratch for gradient accumulation (red.global.add.v4.f32 needs
// 16B alignment; d_out's grad region starts at +1 float so it is NOT aligned).
__device__ float4 g_grad4[MAX_XELEMS / 4];
__device__ float  g_energy;

// ---------------------------------------------------------------------------
// Kernel 1: zero scratch grad + energy accumulator
// ---------------------------------------------------------------------------
__global__ void __launch_bounds__(256) zero_kernel(int n4) {
    int i = blockIdx.x * blockDim.x + threadIdx.x;
    if (i == 0) g_energy = 0.0f;
    int stride = gridDim.x * blockDim.x;
    for (; i < n4; i += stride)
        g_grad4[i] = make_float4(0.f, 0.f, 0.f, 0.f);
}

// ---------------------------------------------------------------------------
// Kernel 2: per-edge gather -> Minkowski inner -> gated force -> vector red
// 16 lanes per edge, one float4 per lane (256B coalesced row reads).
// ---------------------------------------------------------------------------
__global__ void __launch_bounds__(256)
edge_kernel(const float* __restrict__ x,
            const int*   __restrict__ u_idx,
            const int*   __restrict__ v_idx,
            int E, float fmag_coef /* A/NUM_NEG */) {
    const int tid      = blockIdx.x * blockDim.x + threadIdx.x;
    const int lane16   = threadIdx.x & 15;
    const int group    = tid >> 4;
    const int nGroups  = (gridDim.x * blockDim.x) >> 4;
    // shfl member mask for this half-warp (the 16 lanes of this group)
    const unsigned hmask = 0xFFFFu << (threadIdx.x & 16);

    const float4* __restrict__ x4 = (const float4*)x;

    float e_acc = 0.0f;

    for (int e = group; e < E; e += nGroups) {
        const int u = u_idx[e];
        const int v = v_idx[e];

        const float4 xu = x4[u * (DIM / 4) + lane16];
        const float4 xv = x4[v * (DIM / 4) + lane16];

        // Minkowski signature: negate the dim-0 component (lane16==0, .x)
        const float jx = (lane16 == 0) ? -1.0f : 1.0f;

        float p = fmaf(xu.x * jx, xv.x,
                  fmaf(xu.y, xv.y,
                  fmaf(xu.z, xv.z, xu.w * xv.w)));

        // 16-lane tree reduce (stays inside the half-warp)
        p += __shfl_xor_sync(hmask, p, 8);
        p += __shfl_xor_sync(hmask, p, 4);
        p += __shfl_xor_sync(hmask, p, 2);
        p += __shfl_xor_sync(hmask, p, 1);

        const float inner = fminf(p, -1.0f - 1e-7f);
        const float dist  = acoshf(-inner);

        if (dist < 0.1f) {
            const float delta = 0.1f - dist;
            if (lane16 == 0) e_acc += delta * delta;

            const float denom  = sqrtf(inner * inner - 1.0f);
            const float factor = -(fmag_coef * delta) / (denom + 1e-9f);

            // grad[u] += factor * (xv * J);  grad[v] += factor * (xu * J)
            float4 cu, cv;
            cu.x = factor * (xv.x * jx);
            cu.y = factor * xv.y;
            cu.z = factor * xv.z;
            cu.w = factor * xv.w;
            cv.x = factor * (xu.x * jx);
            cv.y = factor * xu.y;
            cv.z = factor * xu.z;
            cv.w = factor * xu.w;

            float4* pu = &g_grad4[u * (DIM / 4) + lane16];
            float4* pv = &g_grad4[v * (DIM / 4) + lane16];
            asm volatile("red.global.add.v4.f32 [%0], {%1,%2,%3,%4};"
                         :: "l"(pu), "f"(cu.x), "f"(cu.y), "f"(cu.z), "f"(cu.w)
                         : "memory");
            asm volatile("red.global.add.v4.f32 [%0], {%1,%2,%3,%4};"
                         :: "l"(pv), "f"(cv.x), "f"(cv.y), "f"(cv.z), "f"(cv.w)
                         : "memory");
        }
    }

    // Energy reduction: warp -> block -> one atomicAdd per block
    for (int o = 16; o >= 1; o >>= 1)
        e_acc += __shfl_xor_sync(0xFFFFFFFFu, e_acc, o);

    __shared__ float s_partial[8];
    const int warp = threadIdx.x >> 5;
    const int lane = threadIdx.x & 31;
    if (lane == 0) s_partial[warp] = e_acc;
    __syncthreads();
    if (threadIdx.x == 0) {
        float bsum = 0.0f;
        const int nwarps = (blockDim.x + 31) >> 5;
        for (int w = 0; w < nwarps; w++) bsum += s_partial[w];
        atomicAdd(&g_energy, bsum);
    }
}

// ---------------------------------------------------------------------------
// Kernel 3: finalize — write energy scalar + copy grad scratch into d_out
// ---------------------------------------------------------------------------
__global__ void __launch_bounds__(256)
finalize_kernel(float* __restrict__ out, int nx, int grad_off, float e_coef) {
    int i = blockIdx.x * blockDim.x + threadIdx.x;
    if (i == 0) {
        for (int k = 0; k < grad_off; k++)  // grad_off is 1 (energy scalar)
            out[k] = e_coef * g_energy;
    }
    const float* __restrict__ g = (const float*)g_grad4;
    const int stride = gridDim.x * blockDim.x;
    for (; i < nx; i += stride)
        out[grad_off + i] = g[i];
}

// ---------------------------------------------------------------------------
extern "C" void kernel_launch(void* const* d_in, const int* in_sizes, int n_in,
                              void* d_out, int out_size) {
    const float* x  = (const float*)d_in[0];
    const int*   ui = (const int*)d_in[1];
    const int*   vi = (const int*)d_in[2];
    float*       out = (float*)d_out;

    const int nx = in_sizes[0];       // N*DIM = 6,400,000
    const int E  = in_sizes[1];       // N*NUM_NEG = 1,000,000
    const int n4 = nx / 4;
    int grad_off = out_size - nx;     // header size before grad (expect 1)
    if (grad_off < 0) grad_off = 0;

    const int   n_nodes  = nx / DIM;
    const float num_neg  = (n_nodes > 0) ? (float)E / (float)n_nodes : 10.0f;
    const float fmag_coef = 100.0f / num_neg;          // A / NUM_NEG
    const float e_coef    = 0.5f * 100.0f / num_neg;   // 0.5*A / NUM_NEG

    {
        int blocks = (n4 + 255) / 256;
        zero_kernel<<<blocks, 256>>>(n4);
    }
    {
        edge_kernel<<<2048, 256>>>(x, ui, vi, E, fmag_coef);
    }
    {
        int blocks = (nx + 255) / 256;
        if (blocks > 25000) blocks = 25000;
        finalize_kernel<<<blocks, 256>>>(out, nx, grad_off, e_coef);
    }
}